// round 6
// baseline (speedup 1.0000x reference)
#include <cuda_runtime.h>
#include <math.h>
#include <string.h>

// GaussianBlurDM, round 5.
//
// out[b] = reflect-conv(reflect-conv(x[b], K_t, axis=H), K_t, axis=W),
// K_t = t-fold self-convolution of the base 11-tap Gaussian (exact DCT-I
// eigenbasis identity for whole-sample symmetric extension).
//
// Both passes are one kernel: vertical reflect-convolution writing output
// transposed (pass1 x[h][w]->mid[w][h], pass2 mid[w][h]->out[h][w]).
// The CTA's full input window lives in shared memory (filled once, coalesced);
// the FMA loop's 16-slot register ring refills from LDS (29 cyc) instead of
// L2 (250-600 cyc), so the scoreboard exposure that capped issue at ~45%
// in rounds 3/4 disappears.

#define BATCH 64
#define CHAN 3
#define IMG 256
#define NT 19
#define NSLOT (NT + 1)     // slot NT = identity (t <= 0 safety)
#define NDPMAX 64          // max padded taps (radius clamp 32)
#define WROWS (NDPMAX + 32)            // 96 smem rows
#define SMEM_BYTES (WROWS * IMG * 4)   // 98304 B -> 2 CTAs/SM

typedef unsigned long long u64;

struct BlurParams {
    u64 K[NSLOT][NDPMAX];   // weight duplicated into both f32 lanes
    int rl[NSLOT];          // left radius (offset of tap 0 = -rl)
    int ndp[NSLOT];         // tap count, multiple of 16, <= NDPMAX
};

__device__ float g_mid[BATCH * CHAN * IMG * IMG];   // ~50 MB transposed scratch

__device__ __forceinline__ int reflect256(int v) {
    v = abs(v);
    return (v > 255) ? (510 - v) : v;
}

__device__ __forceinline__ u64 ffma2(u64 a, u64 b, u64 c) {
    u64 d;
    asm("fma.rn.f32x2 %0, %1, %2, %3;" : "=l"(d) : "l"(a), "l"(b), "l"(c));
    return d;
}

// CTA: 256 threads = 32 output rows x 256 cols (thread: 2 cols x 16 rows).
// Grid: (IMG/32, CHAN, BATCH).
__global__ void __launch_bounds__(256, 2) conv_pass(
    const float* __restrict__ src, float* __restrict__ dst,
    const int* __restrict__ t, const __grid_constant__ BlurParams P)
{
    extern __shared__ float s[];
    const int tid = threadIdx.x;
    const int m0 = blockIdx.x << 5;                  // first output row
    const int bc = blockIdx.z * CHAN + blockIdx.y;
    const float* img = src + ((long)bc << 16);
    float* dimg = dst + ((long)bc << 16);

    const int tb = t[blockIdx.z];
    const int ti = (tb >= 1) ? ((tb > NT) ? (NT - 1) : (tb - 1)) : NT;
    const u64* __restrict__ Kw = P.K[ti];            // constant-bank u64
    const int rl = P.rl[ti];
    const int ndp = P.ndp[ti];
    const int gbase = m0 - rl;
    const int Wt = ndp + 32;                         // rows needed in smem

    // ---- Fill smem rows gbase..gbase+Wt-1 (reflect), coalesced float4. ----
    {
        const float4* img4 = (const float4*)img;
        float4* s4 = (float4*)s;
        const int lane = tid & 63;                   // 64 float4 per row
        for (int q = tid >> 6; q < Wt; q += 4) {     // 4 rows per step
            int g = reflect256(gbase + q);
            s4[(q << 6) + lane] = img4[(g << 6) + lane];
        }
    }
    __syncthreads();

    // ---- Convolution: tap-major ring fed from LDS. ----
    const int cp = tid & 127;                        // column pair 0..127
    const int half = tid >> 7;                       // which 16-row half
    const u64* __restrict__ sc = (const u64*)s + (half << 11) + cp; // row stride 128 u64

    u64 acc[16], ring[16];
    #pragma unroll
    for (int k = 0; k < 16; ++k) acc[k] = 0ull;
    #pragma unroll
    for (int m = 0; m < 16; ++m) ring[m] = sc[m << 7];

    #pragma unroll 1
    for (int jj = 0; jj < ndp; jj += 16) {
        const u64* __restrict__ scp = sc + ((jj + 16) << 7);  // refill base
        #pragma unroll
        for (int u = 0; u < 16; ++u) {
            u64 w = Kw[jj + u];
            #pragma unroll
            for (int k = 0; k < 16; ++k)
                acc[k] = ffma2(ring[(u + k) & 15], w, acc[k]);
            ring[u] = scp[u << 7];                   // row jj+16+u (in smem)
        }
    }

    // ---- Transposed store: column c -> dst[c][m0+half*16 .. +15] (64 B). ----
    const int c0 = cp << 1;
    const int mr = m0 + (half << 4);
    float lo[16], hi[16];
    #pragma unroll
    for (int k = 0; k < 16; ++k) {
        float ax, ay;
        asm("mov.b64 {%0, %1}, %2;" : "=f"(ax), "=f"(ay) : "l"(acc[k]));
        lo[k] = ax; hi[k] = ay;
    }
    float4* d0 = (float4*)(dimg + c0 * IMG + mr);
    float4* d1 = (float4*)(dimg + (c0 + 1) * IMG + mr);
    #pragma unroll
    for (int q = 0; q < 4; ++q) {
        d0[q] = make_float4(lo[4 * q], lo[4 * q + 1], lo[4 * q + 2], lo[4 * q + 3]);
        d1[q] = make_float4(hi[4 * q], hi[4 * q + 1], hi[4 * q + 2], hi[4 * q + 3]);
    }
}

// ---------------------------------------------------------------------------
extern "C" void kernel_launch(void* const* d_in, const int* in_sizes, int n_in,
                              void* d_out, int out_size) {
    const float* x = (const float*)d_in[0];
    const int* t = (const int*)d_in[1];
    float* out = (float*)d_out;

    static BlurParams P;
    memset(&P, 0, sizeof(P));
    {
        // Base kernel, f32-rounded exactly like the reference's _k1d.
        double pdf[11], sum = 0.0;
        for (int i = 0; i < 11; ++i) {
            double xi = -5.0 + (double)i;
            pdf[i] = exp(-0.5 * (xi / 2.0) * (xi / 2.0));
            sum += pdf[i];
        }
        double base[11];
        for (int i = 0; i < 11; ++i)
            base[i] = (double)((float)(pdf[i] / sum));

        double f[220];
        for (int i = 0; i < 220; ++i) f[i] = 0.0;
        for (int i = 0; i < 11; ++i) f[i] = base[i];
        int hw = 5;

        const double TAIL = 1.5e-4;
        for (int tt = 1; tt <= NT; ++tt) {
            // symmetric radius from tail mass
            double acc = 0.0;
            int r = 0;
            for (int a = hw; a >= 1; --a) {
                acc += f[hw + a];
                if (2.0 * acc > TAIL) { r = a; break; }
            }
            int ndp = (2 * r + 1 + 15) & ~15;       // pad taps to 16
            if (ndp > NDPMAX) ndp = NDPMAX;
            int rl = ndp / 2;                        // asymmetric window:
            P.rl[tt - 1] = rl;                       // offsets -rl .. ndp-1-rl
            P.ndp[tt - 1] = ndp;
            for (int jj = 0; jj < ndp; ++jj) {
                int off = jj - rl;
                float w = (off >= -hw && off <= hw) ? (float)f[hw + off] : 0.0f;
                float2 w2 = make_float2(w, w);
                memcpy(&P.K[tt - 1][jj], &w2, 8);
            }
            if (tt < NT) {   // f = f (*) base
                int L = 2 * hw + 1;
                double g[220];
                for (int i = 0; i < 220; ++i) g[i] = 0.0;
                for (int n = 0; n < L; ++n) {
                    double fn = f[n];
                    for (int k = 0; k < 11; ++k) g[n + k] += fn * base[k];
                }
                for (int i = 0; i < 220; ++i) f[i] = g[i];
                hw += 5;
            }
        }
        // Identity slot (t <= 0 safety): unit tap at offset 0 -> exact copy.
        P.rl[NT] = 8;
        P.ndp[NT] = 16;
        float2 one = make_float2(1.0f, 1.0f);
        memcpy(&P.K[NT][8], &one, 8);
    }

    float* mid;
    cudaGetSymbolAddress((void**)&mid, g_mid);

    cudaFuncSetAttribute(conv_pass, cudaFuncAttributeMaxDynamicSharedMemorySize,
                         SMEM_BYTES);

    dim3 block(256);
    dim3 grid(IMG / 32, CHAN, BATCH);   // 8 x 3 x 64 = 1536 CTAs
    conv_pass<<<grid, block, SMEM_BYTES>>>(x, mid, t, P);   // x -> mid (transposed)
    conv_pass<<<grid, block, SMEM_BYTES>>>(mid, out, t, P); // mid -> out
}

// round 7
// speedup vs baseline: 1.2315x; 1.2315x over previous
#include <cuda_runtime.h>
#include <math.h>
#include <string.h>

// GaussianBlurDM, round 6.
//
// out[b] = reflect-conv(reflect-conv(x[b], K_t, axis=H), K_t, axis=W),
// K_t = t-fold self-convolution of the base 11-tap Gaussian (exact DCT-I
// eigenbasis identity for whole-sample symmetric extension).
//
// Two launches of one kernel: vertical reflect-convolution writing output
// transposed (pass1 x[h][w]->mid[w][h], pass2 mid[w][h]->out[h][w]).
// CTA input window staged in smem via cp.async.cg (async, no reg dependence,
// L1-bypass) -> the R5 fill bubble disappears; FMA loop runs a 16-slot
// register ring refilled from LDS with 8-tap granularity.

#define BATCH 64
#define CHAN 3
#define IMG 256
#define NT 19
#define NSLOT (NT + 1)     // slot NT = identity (t <= 0 safety)
#define NDPMAX 64          // max padded taps
#define WROWS (NDPMAX + 32)            // 96 smem rows
#define SMEM_BYTES (WROWS * IMG * 4)   // 98304 B -> 2 CTAs/SM

typedef unsigned long long u64;

struct BlurParams {
    u64 K[NSLOT][NDPMAX];   // weight duplicated into both f32 lanes
    int rl[NSLOT];          // left radius (tap 0 offset = -rl)
    int ndp[NSLOT];         // tap count, multiple of 8, <= NDPMAX
};

__device__ float g_mid[BATCH * CHAN * IMG * IMG];   // ~50 MB transposed scratch

__device__ __forceinline__ int reflect256(int v) {
    v = abs(v);
    return (v > 255) ? (510 - v) : v;
}

__device__ __forceinline__ u64 ffma2(u64 a, u64 b, u64 c) {
    u64 d;
    asm("fma.rn.f32x2 %0, %1, %2, %3;" : "=l"(d) : "l"(a), "l"(b), "l"(c));
    return d;
}

// CTA: 256 threads = 32 output rows x 256 cols (thread: 2 cols x 16 rows).
__global__ void __launch_bounds__(256, 2) conv_pass(
    const float* __restrict__ src, float* __restrict__ dst,
    const int* __restrict__ t, const __grid_constant__ BlurParams P)
{
    extern __shared__ float s[];
    const int tid = threadIdx.x;
    const int m0 = blockIdx.x << 5;                  // first output row
    const int bc = blockIdx.z * CHAN + blockIdx.y;
    const float* img = src + ((long)bc << 16);
    float* dimg = dst + ((long)bc << 16);

    const int tb = t[blockIdx.z];
    const int ti = (tb >= 1) ? ((tb > NT) ? (NT - 1) : (tb - 1)) : NT;
    const u64* __restrict__ Kw = P.K[ti];            // constant bank
    const int rl = P.rl[ti];
    const int ndp = P.ndp[ti];
    const int gbase = m0 - rl;
    const int Wt = ndp + 32;                         // smem rows needed

    // ---- Async fill of smem rows gbase..gbase+Wt-1 (reflect). ----
    {
        const unsigned sbase = (unsigned)__cvta_generic_to_shared(s);
        const int n16 = Wt << 6;                     // Wt * 64 float4
        #pragma unroll 4
        for (int i = tid; i < n16; i += 256) {
            int q = i >> 6, lane = i & 63;
            int g = reflect256(gbase + q);
            const float4* gp = (const float4*)img + (g << 6) + lane;
            unsigned sp = sbase + (unsigned)(i << 4);
            asm volatile("cp.async.cg.shared.global [%0], [%1], 16;"
                         :: "r"(sp), "l"(gp));
        }
        asm volatile("cp.async.commit_group;");
        asm volatile("cp.async.wait_group 0;");
    }
    __syncthreads();

    // ---- Convolution: 16-slot register ring fed from LDS, 8-tap blocks. ----
    const int cp = tid & 127;                        // column pair
    const int half = tid >> 7;                       // 16-row half
    const u64* __restrict__ sc = (const u64*)s + (half << 11) + cp; // row stride 128

    u64 acc[16], ring[16];
    #pragma unroll
    for (int k = 0; k < 16; ++k) acc[k] = 0ull;
    #pragma unroll
    for (int m = 0; m < 16; ++m) ring[m] = sc[m << 7];

    #pragma unroll 1
    for (int jj = 0; jj < ndp; jj += 16) {
        // taps jj .. jj+7 (ring slots k, (1+k)&15, ...)
        #pragma unroll
        for (int u = 0; u < 8; ++u) {
            u64 w = Kw[jj + u];
            #pragma unroll
            for (int k = 0; k < 16; ++k)
                acc[k] = ffma2(ring[(u + k) & 15], w, acc[k]);
            ring[u] = sc[(jj + 16 + u) << 7];        // row jj+16+u
        }
        if (jj + 8 >= ndp) break;
        // taps jj+8 .. jj+15
        #pragma unroll
        for (int u = 8; u < 16; ++u) {
            u64 w = Kw[jj + u];
            #pragma unroll
            for (int k = 0; k < 16; ++k)
                acc[k] = ffma2(ring[(u + k) & 15], w, acc[k]);
            ring[u] = sc[(jj + 16 + u) << 7];
        }
    }

    // ---- Transposed store: column c -> dst[c][mr .. mr+15] (64 B runs). ----
    const int c0 = cp << 1;
    const int mr = m0 + (half << 4);
    float lo[16], hi[16];
    #pragma unroll
    for (int k = 0; k < 16; ++k) {
        float ax, ay;
        asm("mov.b64 {%0, %1}, %2;" : "=f"(ax), "=f"(ay) : "l"(acc[k]));
        lo[k] = ax; hi[k] = ay;
    }
    float4* d0 = (float4*)(dimg + c0 * IMG + mr);
    float4* d1 = (float4*)(dimg + (c0 + 1) * IMG + mr);
    #pragma unroll
    for (int q = 0; q < 4; ++q) {
        d0[q] = make_float4(lo[4 * q], lo[4 * q + 1], lo[4 * q + 2], lo[4 * q + 3]);
        d1[q] = make_float4(hi[4 * q], hi[4 * q + 1], hi[4 * q + 2], hi[4 * q + 3]);
    }
}

// ---------------------------------------------------------------------------
extern "C" void kernel_launch(void* const* d_in, const int* in_sizes, int n_in,
                              void* d_out, int out_size) {
    const float* x = (const float*)d_in[0];
    const int* t = (const int*)d_in[1];
    float* out = (float*)d_out;

    static BlurParams P;
    memset(&P, 0, sizeof(P));
    {
        // Base kernel, f32-rounded exactly like the reference's _k1d.
        double pdf[11], sum = 0.0;
        for (int i = 0; i < 11; ++i) {
            double xi = -5.0 + (double)i;
            pdf[i] = exp(-0.5 * (xi / 2.0) * (xi / 2.0));
            sum += pdf[i];
        }
        double base[11];
        for (int i = 0; i < 11; ++i)
            base[i] = (double)((float)(pdf[i] / sum));

        double f[220];
        for (int i = 0; i < 220; ++i) f[i] = 0.0;
        for (int i = 0; i < 11; ++i) f[i] = base[i];
        int hw = 5;

        const double TAIL = 1.5e-4;
        for (int tt = 1; tt <= NT; ++tt) {
            double acc = 0.0;
            int r = 0;
            for (int a = hw; a >= 1; --a) {
                acc += f[hw + a];
                if (2.0 * acc > TAIL) { r = a; break; }
            }
            int ndp = (2 * r + 1 + 7) & ~7;          // pad taps to 8
            if (ndp > NDPMAX) ndp = NDPMAX;
            int rl = ndp / 2;                        // window: -rl .. ndp-1-rl
            P.rl[tt - 1] = rl;
            P.ndp[tt - 1] = ndp;
            for (int jj = 0; jj < ndp; ++jj) {
                int off = jj - rl;
                float w = (off >= -hw && off <= hw) ? (float)f[hw + off] : 0.0f;
                float2 w2 = make_float2(w, w);
                memcpy(&P.K[tt - 1][jj], &w2, 8);
            }
            if (tt < NT) {   // f = f (*) base
                int L = 2 * hw + 1;
                double g[220];
                for (int i = 0; i < 220; ++i) g[i] = 0.0;
                for (int n = 0; n < L; ++n) {
                    double fn = f[n];
                    for (int k = 0; k < 11; ++k) g[n + k] += fn * base[k];
                }
                for (int i = 0; i < 220; ++i) f[i] = g[i];
                hw += 5;
            }
        }
        // Identity slot (t <= 0 safety): unit tap at offset 0 -> exact copy.
        P.rl[NT] = 4;
        P.ndp[NT] = 8;
        float2 one = make_float2(1.0f, 1.0f);
        memcpy(&P.K[NT][4], &one, 8);
    }

    float* mid;
    cudaGetSymbolAddress((void**)&mid, g_mid);

    cudaFuncSetAttribute(conv_pass, cudaFuncAttributeMaxDynamicSharedMemorySize,
                         SMEM_BYTES);

    dim3 block(256);
    dim3 grid(IMG / 32, CHAN, BATCH);   // 8 x 3 x 64 = 1536 CTAs
    conv_pass<<<grid, block, SMEM_BYTES>>>(x, mid, t, P);   // x -> mid (transposed)
    conv_pass<<<grid, block, SMEM_BYTES>>>(mid, out, t, P); // mid -> out
}

// round 8
// speedup vs baseline: 1.4545x; 1.1811x over previous
#include <cuda_runtime.h>
#include <math.h>
#include <string.h>

// GaussianBlurDM, round 7: FUSED single kernel.
//
// out[b] = reflect-conv(reflect-conv(x[b], K_t, axis=H), K_t, axis=W),
// K_t = t-fold self-convolution of the 11-tap Gaussian (exact DCT-I identity),
// truncated at tail mass 1.5e-4, taps padded to 8.
//
// One CTA = one 32x256 output tile of one (b,c) image:
//   V phase: 16-slot LDG register ring straight from global (no staging fill),
//            result written transposed to smem sv[col][row].
//   H phase: identical ring loop fed from LDS (29cy, fully hidden),
//            coalesced natural-layout store to out. No mid buffer, 1 launch.

#define BATCH 64
#define CHAN 3
#define IMG 256
#define NT 19
#define NSLOT (NT + 1)     // slot NT = identity (t <= 0 safety)
#define NDPMAX 64
#define SVSTRIDE 36        // floats per sv column (32 rows + pad, 16B-friendly)

typedef unsigned long long u64;

struct BlurParams {
    u64 K[NSLOT][NDPMAX];   // weight duplicated into both f32 lanes
    int rl[NSLOT];          // left radius (tap 0 offset = -rl)
    int ndp[NSLOT];         // tap count, multiple of 8, <= NDPMAX
};

__device__ __forceinline__ int reflect256(int v) {
    v = abs(v);
    return (v > 255) ? (510 - v) : v;
}

__device__ __forceinline__ u64 ffma2(u64 a, u64 b, u64 c) {
    u64 d;
    asm("fma.rn.f32x2 %0, %1, %2, %3;" : "=l"(d) : "l"(a), "l"(b), "l"(c));
    return d;
}

__device__ __forceinline__ void unpack2(u64 v, float& x, float& y) {
    asm("mov.b64 {%0, %1}, %2;" : "=f"(x), "=f"(y) : "l"(v));
}

// 8-tap half-block: taps jb..jb+7 against 16-slot ring (phase UB..UB+7),
// refilling slots UB..UB+7 with rows jb+16..jb+23 via LOADEXPR.
#define HALF_BLOCK(UB, jb, LOADEXPR)                                   \
    _Pragma("unroll")                                                  \
    for (int u = UB; u < UB + 8; ++u) {                                \
        u64 w = Kw[(jb) + (u - UB)];                                   \
        _Pragma("unroll")                                              \
        for (int k = 0; k < 16; ++k)                                   \
            acc[k] = ffma2(ring[(u + k) & 15], w, acc[k]);             \
        { int q = (jb) + 16 + (u - UB); ring[u & 15] = (LOADEXPR); }   \
    }

__global__ void __launch_bounds__(256, 2) blur_fused(
    const float* __restrict__ src, float* __restrict__ dst,
    const int* __restrict__ t, const __grid_constant__ BlurParams P)
{
    __shared__ float sv[IMG * SVSTRIDE];             // 36864 B

    const int tid = threadIdx.x;
    const int m0 = blockIdx.x << 5;                  // tile's first output row
    const int bc = blockIdx.z * CHAN + blockIdx.y;
    const float* img = src + ((long)bc << 16);
    float* gout = dst + ((long)bc << 16);

    const int tb = t[blockIdx.z];
    const int ti = (tb >= 1) ? ((tb > NT) ? (NT - 1) : (tb - 1)) : NT;
    const u64* __restrict__ Kw = P.K[ti];            // constant bank
    const int rl = P.rl[ti];
    const int ndp = P.ndp[ti];

    u64 acc[16], ring[16];

    // ================= V phase: global LDG ring, conv over rows =============
    {
        const int cp = tid & 127;                    // column pair 0..127
        const int half = tid >> 7;                   // 16-row half
        const u64* __restrict__ scol = (const u64*)img + cp;   // row stride 128
        const int vb = m0 + (half << 4) - rl;        // first input row

        #pragma unroll
        for (int k = 0; k < 16; ++k) acc[k] = 0ull;
        #pragma unroll
        for (int m = 0; m < 16; ++m)
            ring[m] = __ldg(scol + (reflect256(vb + m) << 7));

        #pragma unroll 1
        for (int jj = 0; jj < ndp; jj += 16) {
            HALF_BLOCK(0, jj, __ldg(scol + (reflect256(vb + q) << 7)))
            if (jj + 8 >= ndp) break;
            HALF_BLOCK(8, jj + 8, __ldg(scol + (reflect256(vb + q) << 7)))
        }

        // Store transposed to smem: col c -> sv[c][mr..mr+15].
        const int c0 = cp << 1;
        const int mr = half << 4;
        float lo[16], hi[16];
        #pragma unroll
        for (int k = 0; k < 16; ++k) unpack2(acc[k], lo[k], hi[k]);
        float4* p0 = (float4*)(sv + c0 * SVSTRIDE + mr);
        float4* p1 = (float4*)(sv + (c0 + 1) * SVSTRIDE + mr);
        #pragma unroll
        for (int q = 0; q < 4; ++q) {
            p0[q] = make_float4(lo[4*q], lo[4*q+1], lo[4*q+2], lo[4*q+3]);
            p1[q] = make_float4(hi[4*q], hi[4*q+1], hi[4*q+2], hi[4*q+3]);
        }
    }

    __syncthreads();

    // ================= H phase: LDS ring over sv, conv over cols ============
    {
        const int rp = tid & 15;                     // row pair 0..15
        const int cg = tid >> 4;                     // 16-col group 0..15
        const u64* __restrict__ sb = (const u64*)sv + rp;  // col q: sb[q*18]
        const int qb = (cg << 4) - rl;               // first input col

        #pragma unroll
        for (int k = 0; k < 16; ++k) acc[k] = 0ull;
        #pragma unroll
        for (int m = 0; m < 16; ++m)
            ring[m] = sb[reflect256(qb + m) * (SVSTRIDE / 2)];

        #pragma unroll 1
        for (int jj = 0; jj < ndp; jj += 16) {
            HALF_BLOCK(0, jj, sb[reflect256(qb + q) * (SVSTRIDE / 2)])
            if (jj + 8 >= ndp) break;
            HALF_BLOCK(8, jj + 8, sb[reflect256(qb + q) * (SVSTRIDE / 2)])
        }

        // Natural-layout store: rows m0+2rp, m0+2rp+1, cols cg*16..+15.
        float lo[16], hi[16];
        #pragma unroll
        for (int k = 0; k < 16; ++k) unpack2(acc[k], lo[k], hi[k]);
        float4* d0 = (float4*)(gout + (m0 + 2 * rp) * IMG + (cg << 4));
        float4* d1 = (float4*)(gout + (m0 + 2 * rp + 1) * IMG + (cg << 4));
        #pragma unroll
        for (int q = 0; q < 4; ++q) {
            d0[q] = make_float4(lo[4*q], lo[4*q+1], lo[4*q+2], lo[4*q+3]);
            d1[q] = make_float4(hi[4*q], hi[4*q+1], hi[4*q+2], hi[4*q+3]);
        }
    }
}

// ---------------------------------------------------------------------------
extern "C" void kernel_launch(void* const* d_in, const int* in_sizes, int n_in,
                              void* d_out, int out_size) {
    const float* x = (const float*)d_in[0];
    const int* t = (const int*)d_in[1];
    float* out = (float*)d_out;

    static BlurParams P;
    memset(&P, 0, sizeof(P));
    {
        // Base kernel, f32-rounded exactly like the reference's _k1d.
        double pdf[11], sum = 0.0;
        for (int i = 0; i < 11; ++i) {
            double xi = -5.0 + (double)i;
            pdf[i] = exp(-0.5 * (xi / 2.0) * (xi / 2.0));
            sum += pdf[i];
        }
        double base[11];
        for (int i = 0; i < 11; ++i)
            base[i] = (double)((float)(pdf[i] / sum));

        double f[220];
        for (int i = 0; i < 220; ++i) f[i] = 0.0;
        for (int i = 0; i < 11; ++i) f[i] = base[i];
        int hw = 5;

        const double TAIL = 1.5e-4;
        for (int tt = 1; tt <= NT; ++tt) {
            double acc = 0.0;
            int r = 0;
            for (int a = hw; a >= 1; --a) {
                acc += f[hw + a];
                if (2.0 * acc > TAIL) { r = a; break; }
            }
            int ndp = (2 * r + 1 + 7) & ~7;          // pad taps to 8
            if (ndp > NDPMAX) ndp = NDPMAX;
            int rl = ndp / 2;                        // window: -rl .. ndp-1-rl
            P.rl[tt - 1] = rl;
            P.ndp[tt - 1] = ndp;
            for (int jj = 0; jj < ndp; ++jj) {
                int off = jj - rl;
                float w = (off >= -hw && off <= hw) ? (float)f[hw + off] : 0.0f;
                float2 w2 = make_float2(w, w);
                memcpy(&P.K[tt - 1][jj], &w2, 8);
            }
            if (tt < NT) {   // f = f (*) base
                int L = 2 * hw + 1;
                double g[220];
                for (int i = 0; i < 220; ++i) g[i] = 0.0;
                for (int n = 0; n < L; ++n) {
                    double fn = f[n];
                    for (int k = 0; k < 11; ++k) g[n + k] += fn * base[k];
                }
                for (int i = 0; i < 220; ++i) f[i] = g[i];
                hw += 5;
            }
        }
        // Identity slot (t <= 0 safety): unit tap at offset 0 -> exact copy.
        P.rl[NT] = 4;
        P.ndp[NT] = 8;
        float2 one = make_float2(1.0f, 1.0f);
        memcpy(&P.K[NT][4], &one, 8);
    }

    dim3 block(256);
    dim3 grid(IMG / 32, CHAN, BATCH);   // 8 x 3 x 64 = 1536 CTAs
    blur_fused<<<grid, block>>>(x, out, t, P);
}

// round 9
// speedup vs baseline: 1.5295x; 1.0516x over previous
#include <cuda_runtime.h>
#include <math.h>
#include <string.h>

// GaussianBlurDM, round 8: fused kernel, BOTH phases LDS-fed.
//
// out[b] = reflect-conv(reflect-conv(x[b], K_t, axis=H), K_t, axis=W),
// K_t = t-fold self-convolution of the 11-tap Gaussian (exact DCT-I identity),
// truncated at tail mass 1.5e-4, taps padded to 16 with true tail weights.
//
// One CTA = 32x256 output tile:
//   V phase: input streamed in 16-row chunks through a 4-buffer cp.async.cg
//            ring (compute chunk J overlaps load of chunk J+4); 16-slot
//            register ring refills from LDS with immediate offsets.
//            Result written transposed to smem sv[col][row].
//   H phase: identical ring loop over sv (interior column groups take a
//            reflect-free fast path), coalesced natural-layout store.

#define BATCH 64
#define CHAN 3
#define IMG 256
#define NT 19
#define NSLOT (NT + 1)     // slot NT = identity (t <= 0 safety)
#define NDPMAX 64
#define SVSTRIDE 36        // floats per sv column
#define SV_U64 (SVSTRIDE / 2)
#define NBUF 4
#define SV_BYTES (IMG * SVSTRIDE * 4)            // 36864
#define SBUF_BYTES (NBUF * 16 * IMG * 4)         // 65536
#define SMEM_BYTES (SV_BYTES + SBUF_BYTES)       // 102400 -> 2 CTAs/SM

typedef unsigned long long u64;

struct BlurParams {
    u64 K[NSLOT][NDPMAX];   // weight duplicated into both f32 lanes
    int rl[NSLOT];          // left radius (tap 0 offset = -rl)
    int ndp[NSLOT];         // tap count, multiple of 16, <= NDPMAX
};

__device__ __forceinline__ int reflect256(int v) {
    v = abs(v);
    return (v > 255) ? (510 - v) : v;
}

__device__ __forceinline__ u64 ffma2(u64 a, u64 b, u64 c) {
    u64 d;
    asm("fma.rn.f32x2 %0, %1, %2, %3;" : "=l"(d) : "l"(a), "l"(b), "l"(c));
    return d;
}

__device__ __forceinline__ void unpack2(u64 v, float& x, float& y) {
    asm("mov.b64 {%0, %1}, %2;" : "=f"(x), "=f"(y) : "l"(v));
}

// Issue async copy of staged chunk c (16 rows x 256 floats) into buffer c&3.
__device__ __forceinline__ void issue_chunk(
    unsigned sbuf_sa, const float* img, int gbase, int c, int tid)
{
    const int lane = tid & 63;
    const int r0 = (c << 4) + (tid >> 6);
    unsigned sp = sbuf_sa + ((c & 3) << 14) + ((tid >> 6) << 10) + (lane << 4);
    #pragma unroll
    for (int s = 0; s < 4; ++s) {
        int g = reflect256(gbase + r0 + s * 4);
        const float4* gp = (const float4*)img + (g << 6) + lane;
        asm volatile("cp.async.cg.shared.global [%0], [%1], 16;"
                     :: "r"(sp + (s << 12)), "l"(gp));
    }
    asm volatile("cp.async.commit_group;");
}

__global__ void __launch_bounds__(256, 2) blur_fused(
    const float* __restrict__ src, float* __restrict__ dst,
    const int* __restrict__ t, const __grid_constant__ BlurParams P)
{
    extern __shared__ float smem[];
    float* sv = smem;                               // transposed intermediate
    float* sbuf = smem + IMG * SVSTRIDE;            // staging ring
    const unsigned sbuf_sa = (unsigned)__cvta_generic_to_shared(sbuf);

    const int tid = threadIdx.x;
    const int m0 = blockIdx.x << 5;                 // tile's first output row
    const int bc = blockIdx.z * CHAN + blockIdx.y;
    const float* img = src + ((long)bc << 16);
    float* gout = dst + ((long)bc << 16);

    const int tb = t[blockIdx.z];
    const int ti = (tb >= 1) ? ((tb > NT) ? (NT - 1) : (tb - 1)) : NT;
    const u64* __restrict__ Kw = P.K[ti];           // constant bank
    const int rl = P.rl[ti];
    const int ndp = P.ndp[ti];
    const int NC = ndp >> 4;                        // tap chunks (1..4)
    const int NCH = NC + 2;                         // staged chunks (3..6)
    const int gbase = m0 - rl;

    u64 acc[16], ring[16];

    // ---- Prologue: stream first chunks. Need chunks 0..2 before compute. ----
    {
        int ni = (NCH < 4) ? NCH : 4;
        for (int c = 0; c < ni; ++c) issue_chunk(sbuf_sa, img, gbase, c, tid);
        if (ni == 4) asm volatile("cp.async.wait_group 1;");
        else         asm volatile("cp.async.wait_group 0;");
    }
    __syncthreads();

    // ================= V phase: LDS ring over staged chunks =================
    {
        const int cp_ = tid & 127;                  // column pair
        const int half = tid >> 7;                  // 16-row half
        const u64* __restrict__ sb64 = (const u64*)sbuf;

        #pragma unroll
        for (int k = 0; k < 16; ++k) acc[k] = 0ull;
        {   // ring init from staged chunk 'half'
            const u64* p0 = sb64 + (half << 11) + cp_;
            #pragma unroll
            for (int m = 0; m < 16; ++m) ring[m] = p0[m << 7];
        }

        #pragma unroll 1
        for (int J = 0; J < NC; ++J) {
            // refills come from staged chunk J+1+half (resident)
            const u64* pb = sb64 + (((J + 1 + half) & 3) << 11) + cp_;
            #pragma unroll
            for (int u = 0; u < 16; ++u) {
                u64 w = Kw[(J << 4) + u];
                #pragma unroll
                for (int k = 0; k < 16; ++k)
                    acc[k] = ffma2(ring[(u + k) & 15], w, acc[k]);
                ring[u] = pb[u << 7];
            }
            // overlap: prefetch chunk J+4 into buffer J&3 (chunk J is dead)
            if (J + 4 < NCH) {
                issue_chunk(sbuf_sa, img, gbase, J + 4, tid);
                asm volatile("cp.async.wait_group 1;");
            } else {
                asm volatile("cp.async.wait_group 0;");
            }
            __syncthreads();
        }

        // Store transposed to sv: col c -> sv[c][mr..mr+15].
        const int c0 = cp_ << 1;
        const int mr = half << 4;
        float lo[16], hi[16];
        #pragma unroll
        for (int k = 0; k < 16; ++k) unpack2(acc[k], lo[k], hi[k]);
        float4* p0 = (float4*)(sv + c0 * SVSTRIDE + mr);
        float4* p1 = (float4*)(sv + (c0 + 1) * SVSTRIDE + mr);
        #pragma unroll
        for (int q = 0; q < 4; ++q) {
            p0[q] = make_float4(lo[4*q], lo[4*q+1], lo[4*q+2], lo[4*q+3]);
            p1[q] = make_float4(hi[4*q], hi[4*q+1], hi[4*q+2], hi[4*q+3]);
        }
    }

    __syncthreads();

    // ================= H phase: LDS ring over sv =============================
    {
        const int rp = tid & 15;                    // row pair
        const int cg = tid >> 4;                    // 16-col group
        const u64* __restrict__ sb = (const u64*)sv + rp;
        const int qb = (cg << 4) - rl;              // first input col

        #pragma unroll
        for (int k = 0; k < 16; ++k) acc[k] = 0ull;

        if (qb >= 0 && qb + ndp + 15 <= 255) {
            // interior fast path: linear columns, immediate offsets
            const u64* pH = sb + qb * SV_U64;
            #pragma unroll
            for (int m = 0; m < 16; ++m) ring[m] = pH[m * SV_U64];
            #pragma unroll 1
            for (int J = 0; J < NC; ++J) {
                const u64* pb = pH + ((J << 4) + 16) * SV_U64;
                #pragma unroll
                for (int u = 0; u < 16; ++u) {
                    u64 w = Kw[(J << 4) + u];
                    #pragma unroll
                    for (int k = 0; k < 16; ++k)
                        acc[k] = ffma2(ring[(u + k) & 15], w, acc[k]);
                    ring[u] = pb[u * SV_U64];
                }
            }
        } else {
            // boundary path: reflected columns
            #pragma unroll
            for (int m = 0; m < 16; ++m)
                ring[m] = sb[reflect256(qb + m) * SV_U64];
            #pragma unroll 1
            for (int J = 0; J < NC; ++J) {
                const int rb = qb + (J << 4) + 16;
                #pragma unroll
                for (int u = 0; u < 16; ++u) {
                    u64 w = Kw[(J << 4) + u];
                    #pragma unroll
                    for (int k = 0; k < 16; ++k)
                        acc[k] = ffma2(ring[(u + k) & 15], w, acc[k]);
                    ring[u] = sb[reflect256(rb + u) * SV_U64];
                }
            }
        }

        // Natural-layout store: rows m0+2rp(+1), cols cg*16..+15.
        float lo[16], hi[16];
        #pragma unroll
        for (int k = 0; k < 16; ++k) unpack2(acc[k], lo[k], hi[k]);
        float4* d0 = (float4*)(gout + (m0 + 2 * rp) * IMG + (cg << 4));
        float4* d1 = (float4*)(gout + (m0 + 2 * rp + 1) * IMG + (cg << 4));
        #pragma unroll
        for (int q = 0; q < 4; ++q) {
            d0[q] = make_float4(lo[4*q], lo[4*q+1], lo[4*q+2], lo[4*q+3]);
            d1[q] = make_float4(hi[4*q], hi[4*q+1], hi[4*q+2], hi[4*q+3]);
        }
    }
}

// ---------------------------------------------------------------------------
extern "C" void kernel_launch(void* const* d_in, const int* in_sizes, int n_in,
                              void* d_out, int out_size) {
    const float* x = (const float*)d_in[0];
    const int* t = (const int*)d_in[1];
    float* out = (float*)d_out;

    static BlurParams P;
    memset(&P, 0, sizeof(P));
    {
        // Base kernel, f32-rounded exactly like the reference's _k1d.
        double pdf[11], sum = 0.0;
        for (int i = 0; i < 11; ++i) {
            double xi = -5.0 + (double)i;
            pdf[i] = exp(-0.5 * (xi / 2.0) * (xi / 2.0));
            sum += pdf[i];
        }
        double base[11];
        for (int i = 0; i < 11; ++i)
            base[i] = (double)((float)(pdf[i] / sum));

        double f[220];
        for (int i = 0; i < 220; ++i) f[i] = 0.0;
        for (int i = 0; i < 11; ++i) f[i] = base[i];
        int hw = 5;

        const double TAIL = 1.5e-4;
        for (int tt = 1; tt <= NT; ++tt) {
            double acc = 0.0;
            int r = 0;
            for (int a = hw; a >= 1; --a) {
                acc += f[hw + a];
                if (2.0 * acc > TAIL) { r = a; break; }
            }
            int ndp = (2 * r + 1 + 15) & ~15;        // pad taps to 16
            if (ndp > NDPMAX) ndp = NDPMAX;
            int rl = ndp / 2;                        // window: -rl .. ndp-1-rl
            P.rl[tt - 1] = rl;
            P.ndp[tt - 1] = ndp;
            for (int jj = 0; jj < ndp; ++jj) {
                int off = jj - rl;
                float w = (off >= -hw && off <= hw) ? (float)f[hw + off] : 0.0f;
                float2 w2 = make_float2(w, w);
                memcpy(&P.K[tt - 1][jj], &w2, 8);
            }
            if (tt < NT) {   // f = f (*) base
                int L = 2 * hw + 1;
                double g[220];
                for (int i = 0; i < 220; ++i) g[i] = 0.0;
                for (int n = 0; n < L; ++n) {
                    double fn = f[n];
                    for (int k = 0; k < 11; ++k) g[n + k] += fn * base[k];
                }
                for (int i = 0; i < 220; ++i) f[i] = g[i];
                hw += 5;
            }
        }
        // Identity slot (t <= 0 safety): unit tap at offset 0 -> exact copy.
        P.rl[NT] = 8;
        P.ndp[NT] = 16;
        float2 one = make_float2(1.0f, 1.0f);
        memcpy(&P.K[NT][8], &one, 8);
    }

    cudaFuncSetAttribute(blur_fused, cudaFuncAttributeMaxDynamicSharedMemorySize,
                         SMEM_BYTES);

    dim3 block(256);
    dim3 grid(IMG / 32, CHAN, BATCH);   // 8 x 3 x 64 = 1536 CTAs
    blur_fused<<<grid, block, SMEM_BYTES>>>(x, out, t, P);
}